// round 4
// baseline (speedup 1.0000x reference)
#include <cuda_runtime.h>
#include <cstdint>

// Output (64, 64, 62, 62) f32. Only out[b, 0, 0:2, 0:62] is nonzero — the
// first 124 floats (496 B, 16B-aligned) of every batch slice (984064 B).
// Zero region per batch: bytes [496, 984064) = 983568 B = 30 x 32KB + 528 B
// => 31 bulk-store ops per batch, 64*31 = 1984 ops total.
// Blocks [0,31): strip compute. Blocks [31, 31+496): 4 TMA bulk-store ops each.

#define NSTRIP      31
#define NFILL       496
#define OPS_TOTAL   1984          // 64 batches * 31 ops
#define BATCH_BYTES 984064u
#define STRIP_BYTES 496u
#define OP_BYTES    32768u
#define TAIL_BYTES  528u          // 983568 - 30*32768
#define SMEM_ZB4    2048          // 32 KB of zeros

__device__ __forceinline__ uint32_t smem_u32(const void* p) {
    uint32_t a;
    asm("{ .reg .u64 t; cvta.to.shared.u64 t, %1; cvt.u32.u64 %0, t; }"
        : "=r"(a) : "l"(p));
    return a;
}

__global__ void __launch_bounds__(256)
wg_fused(const float* __restrict__ x,
         const float* __restrict__ filt,
         float* __restrict__ out) {
    __shared__ float4 zbuf[SMEM_ZB4];          // 32 KB zero source for TMA
    __shared__ float sm[2][16];
    __shared__ float Y[4];

    if (blockIdx.x >= NSTRIP) {
        // ---------------- TMA bulk-store zero-fill ----------------
        const float4 z = make_float4(0.f, 0.f, 0.f, 0.f);
#pragma unroll
        for (int i = 0; i < SMEM_ZB4 / 256; ++i)
            zbuf[threadIdx.x + i * 256] = z;
        __syncthreads();

        if (threadIdx.x == 0) {
            asm volatile("fence.proxy.async.shared::cta;" ::: "memory");
            const uint32_t src = smem_u32(zbuf);
            const int zb = blockIdx.x - NSTRIP;
            char* base = (char*)out;
#pragma unroll
            for (int k = 0; k < 4; ++k) {
                const int o = zb + k * NFILL;          // < OPS_TOTAL always
                const int batch = o / 31;
                const int slot  = o % 31;
                char* dst = base + (size_t)batch * BATCH_BYTES
                                 + STRIP_BYTES + (uint32_t)slot * OP_BYTES;
                const uint32_t sz = (slot < 30) ? OP_BYTES : TAIL_BYTES;
                asm volatile(
                    "cp.async.bulk.global.shared::cta.bulk_group [%0], [%1], %2;"
                    :: "l"(dst), "r"(src), "r"(sz) : "memory");
            }
            asm volatile("cp.async.bulk.commit_group;" ::: "memory");
            asm volatile("cp.async.bulk.wait_group 0;" ::: "memory");
        }
        return;
    }

    // ---------------- strip path: tile u = blockIdx.x ----------------
    const int u = blockIdx.x;       // 0..30

    if (threadIdx.x < 64) {
        const int c = threadIdx.x;  // channel

        // W = filters[0, c]
        float W[3][3];
#pragma unroll
        for (int j = 0; j < 3; ++j)
#pragma unroll
            for (int k = 0; k < 3; ++k)
                W[j][k] = filt[c * 9 + j * 3 + k];

        // U = G W G^T,  G = [[1,0,0],[.5,.5,1.2],[.5,-.5,.5],[0,0,1]]
        float s[4][3];
#pragma unroll
        for (int k = 0; k < 3; ++k) {
            s[0][k] = W[0][k];
            s[1][k] = 0.5f * W[0][k] + 0.5f * W[1][k] + 1.2f * W[2][k];
            s[2][k] = 0.5f * W[0][k] - 0.5f * W[1][k] + 0.5f * W[2][k];
            s[3][k] = W[2][k];
        }
        float U[4][4];
#pragma unroll
        for (int i = 0; i < 4; ++i) {
            U[i][0] = s[i][0];
            U[i][1] = 0.5f * s[i][0] + 0.5f * s[i][1] + 1.2f * s[i][2];
            U[i][2] = 0.5f * s[i][0] - 0.5f * s[i][1] + 0.5f * s[i][2];
            U[i][3] = s[i][2];
        }

        // X = x[0, c, 0:4, 2u:2u+4]
        float X[4][4];
        const float* xp = x + c * 4096 + 2 * u;
#pragma unroll
        for (int j = 0; j < 4; ++j)
#pragma unroll
            for (int k = 0; k < 4; ++k)
                X[j][k] = xp[j * 64 + k];

        // t = B^T X ; B^T rows: (1,0,0,0) (0,1,-1,1) (-1,1,1,0) (0,0,0,-1)
        float t[4][4];
#pragma unroll
        for (int k = 0; k < 4; ++k) {
            t[0][k] = X[0][k];
            t[1][k] = X[1][k] - X[2][k] + X[3][k];
            t[2][k] = -X[0][k] + X[1][k] + X[2][k];
            t[3][k] = -X[3][k];
        }
        // V = t B ; M_c = U .* V ; accumulate over channels
        float Macc[16];
#pragma unroll
        for (int i = 0; i < 4; ++i) {
            float v0 = t[i][0];
            float v1 = t[i][1] - t[i][2] + t[i][3];
            float v2 = -t[i][0] + t[i][1] + t[i][2];
            float v3 = -t[i][3];
            Macc[i * 4 + 0] = U[i][0] * v0;
            Macc[i * 4 + 1] = U[i][1] * v1;
            Macc[i * 4 + 2] = U[i][2] * v2;
            Macc[i * 4 + 3] = U[i][3] * v3;
        }

        // reduce 16 values over 64 channels (2 warps)
#pragma unroll
        for (int off = 16; off > 0; off >>= 1)
#pragma unroll
            for (int e = 0; e < 16; ++e)
                Macc[e] += __shfl_down_sync(0xffffffffu, Macc[e], off);

        const int warp = threadIdx.x >> 5;
        const int lane = threadIdx.x & 31;
        if (lane == 0) {
#pragma unroll
            for (int e = 0; e < 16; ++e) sm[warp][e] = Macc[e];
        }
    }
    __syncthreads();
    if (threadIdx.x == 0) {
        float M[4][4];
#pragma unroll
        for (int e = 0; e < 16; ++e) M[e >> 2][e & 3] = sm[0][e] + sm[1][e];
        // Y = AT M AT^T ; AT = [[1,1,1,0],[0,1,-1,-1]]
        float T0[4], T1[4];
#pragma unroll
        for (int k = 0; k < 4; ++k) {
            T0[k] = M[0][k] + M[1][k] + M[2][k];
            T1[k] = M[1][k] - M[2][k] - M[3][k];
        }
        Y[0] = T0[0] + T0[1] + T0[2];
        Y[1] = T0[1] - T0[2] - T0[3];
        Y[2] = T1[0] + T1[1] + T1[2];
        Y[3] = T1[1] - T1[2] - T1[3];
    }
    __syncthreads();

    // fan out to all 64 batches: out[b, 0, {0,1}, 2u+{0,1}]
    if (threadIdx.x < 64) {
        const int b = threadIdx.x;
        float* op = out + (size_t)b * 246016 + 2 * u;
        op[0]  = Y[0];
        op[1]  = Y[1];
        op[62] = Y[2];
        op[63] = Y[3];
    }
}

extern "C" void kernel_launch(void* const* d_in, const int* in_sizes, int n_in,
                              void* d_out, int out_size) {
    const float* x    = (const float*)d_in[0];   // (64,64,64,64) f32
    const float* filt = (const float*)d_in[1];   // (64,64,3,3)   f32
    float* out = (float*)d_out;                  // (64,64,62,62) f32

    wg_fused<<<NSTRIP + NFILL, 256>>>(x, filt, out);
}

// round 5
// speedup vs baseline: 1.2443x; 1.2443x over previous
#include <cuda_runtime.h>

// Output (64, 64, 62, 62) f32. Only out[b, 0, 0:2, 0:62] is nonzero — the
// first 124 floats of every batch slice (batch stride 246016 floats).
//
// Plan: graph memset node zeroes the whole 63 MB output via the CE fill path
// (bypassing the SM STG->L2 store wall measured at 48% LTS in R1-R3), then a
// tiny 31-block kernel overwrites the nonzero strip (stream-ordered after).

__global__ void wg_strip(const float* __restrict__ x,
                         const float* __restrict__ filt,
                         float* __restrict__ out) {
    const int u = blockIdx.x;   // tile column 0..30
    const int c = threadIdx.x;  // channel 0..63

    __shared__ float sm[2][16];
    __shared__ float Y[4];

    // W = filters[0, c]
    float W[3][3];
#pragma unroll
    for (int j = 0; j < 3; ++j)
#pragma unroll
        for (int k = 0; k < 3; ++k)
            W[j][k] = filt[c * 9 + j * 3 + k];

    // U = G W G^T,  G = [[1,0,0],[.5,.5,1.2],[.5,-.5,.5],[0,0,1]]
    float s[4][3];
#pragma unroll
    for (int k = 0; k < 3; ++k) {
        s[0][k] = W[0][k];
        s[1][k] = 0.5f * W[0][k] + 0.5f * W[1][k] + 1.2f * W[2][k];
        s[2][k] = 0.5f * W[0][k] - 0.5f * W[1][k] + 0.5f * W[2][k];
        s[3][k] = W[2][k];
    }
    float U[4][4];
#pragma unroll
    for (int i = 0; i < 4; ++i) {
        U[i][0] = s[i][0];
        U[i][1] = 0.5f * s[i][0] + 0.5f * s[i][1] + 1.2f * s[i][2];
        U[i][2] = 0.5f * s[i][0] - 0.5f * s[i][1] + 0.5f * s[i][2];
        U[i][3] = s[i][2];
    }

    // X = x[0, c, 0:4, 2u:2u+4]
    float X[4][4];
    const float* xp = x + c * 4096 + 2 * u;
#pragma unroll
    for (int j = 0; j < 4; ++j)
#pragma unroll
        for (int k = 0; k < 4; ++k)
            X[j][k] = xp[j * 64 + k];

    // t = B^T X ; B^T rows: (1,0,0,0) (0,1,-1,1) (-1,1,1,0) (0,0,0,-1)
    float t[4][4];
#pragma unroll
    for (int k = 0; k < 4; ++k) {
        t[0][k] = X[0][k];
        t[1][k] = X[1][k] - X[2][k] + X[3][k];
        t[2][k] = -X[0][k] + X[1][k] + X[2][k];
        t[3][k] = -X[3][k];
    }
    // V = t B ; M_c = U .* V ; accumulate over channels
    float Macc[16];
#pragma unroll
    for (int i = 0; i < 4; ++i) {
        float v0 = t[i][0];
        float v1 = t[i][1] - t[i][2] + t[i][3];
        float v2 = -t[i][0] + t[i][1] + t[i][2];
        float v3 = -t[i][3];
        Macc[i * 4 + 0] = U[i][0] * v0;
        Macc[i * 4 + 1] = U[i][1] * v1;
        Macc[i * 4 + 2] = U[i][2] * v2;
        Macc[i * 4 + 3] = U[i][3] * v3;
    }

    // reduce 16 values over 64 channels (2 warps)
#pragma unroll
    for (int off = 16; off > 0; off >>= 1)
#pragma unroll
        for (int e = 0; e < 16; ++e)
            Macc[e] += __shfl_down_sync(0xffffffffu, Macc[e], off);

    const int warp = threadIdx.x >> 5;
    const int lane = threadIdx.x & 31;
    if (lane == 0) {
#pragma unroll
        for (int e = 0; e < 16; ++e) sm[warp][e] = Macc[e];
    }
    __syncthreads();
    if (threadIdx.x == 0) {
        float M[4][4];
#pragma unroll
        for (int e = 0; e < 16; ++e) M[e >> 2][e & 3] = sm[0][e] + sm[1][e];
        // Y = AT M AT^T ; AT = [[1,1,1,0],[0,1,-1,-1]]
        float T0[4], T1[4];
#pragma unroll
        for (int k = 0; k < 4; ++k) {
            T0[k] = M[0][k] + M[1][k] + M[2][k];
            T1[k] = M[1][k] - M[2][k] - M[3][k];
        }
        Y[0] = T0[0] + T0[1] + T0[2];
        Y[1] = T0[1] - T0[2] - T0[3];
        Y[2] = T1[0] + T1[1] + T1[2];
        Y[3] = T1[1] - T1[2] - T1[3];
    }
    __syncthreads();

    // fan out to all 64 batches: out[b, 0, {0,1}, 2u+{0,1}]
    const int b = threadIdx.x;
    float* op = out + (size_t)b * 246016 + 2 * u;
    op[0]  = Y[0];
    op[1]  = Y[1];
    op[62] = Y[2];
    op[63] = Y[3];
}

extern "C" void kernel_launch(void* const* d_in, const int* in_sizes, int n_in,
                              void* d_out, int out_size) {
    const float* x    = (const float*)d_in[0];   // (64,64,64,64) f32
    const float* filt = (const float*)d_in[1];   // (64,64,3,3)   f32
    float* out = (float*)d_out;                  // (64,64,62,62) f32

    // Graph-capturable async memset node: zero the whole output via the
    // copy-engine fill path (bypasses the SM STG->L2 wall).
    cudaMemsetAsync(d_out, 0, (size_t)out_size * sizeof(float), 0);

    // Stream-ordered after the memset: write the only nonzero strip.
    wg_strip<<<31, 64>>>(x, filt, out);
}

// round 6
// speedup vs baseline: 1.6182x; 1.3005x over previous
#include <cuda_runtime.h>

// Output (64, 64, 62, 62) f32, batch slice = 246016 floats = 61504 float4.
// Only out[b, 0, 0:2, 0:62] (first 124 floats = 31 f4) of each batch is
// nonzero. Zero region per batch: f4 [31, 61504).
//   fill blocks: 240 per batch, 256 thr, ONE unconditional f4 store each
//                -> cover f4 [31, 61471) per batch, no predicates.
//   strip blocks (0..30): threads 0..63 compute the Winograd strip for tile
//                u = blockIdx.x; threads 64..255 zero the per-batch tails
//                f4 [61471, 61504) (64 batches x 33 f4 = 2112 stores over
//                31 x 192 = 5952 spare threads).
// All write sets disjoint -> single kernel, no races.

#define NSTRIP    31
#define BATCH_F4  61504
#define FILL_BASE 31       // first zeroed f4 in each batch
#define FPB       240      // fill blocks per batch
#define TAIL_F4   33       // 61504 - 31 - 240*256
#define TAIL_BEG  61471    // 31 + 240*256
#define NTAIL     (64 * TAIL_F4)   // 2112

__global__ void __launch_bounds__(256)
wg_fused(const float* __restrict__ x,
         const float* __restrict__ filt,
         float* __restrict__ out) {
    if (blockIdx.x >= NSTRIP) {
        // ------------- fill path: one unconditional 16B store -------------
        const int zb    = blockIdx.x - NSTRIP;
        const int batch = zb / FPB;
        const int chunk = zb - batch * FPB;
        float4* o4 = (float4*)out;
        o4[(size_t)batch * BATCH_F4 + FILL_BASE + chunk * 256 + threadIdx.x] =
            make_float4(0.f, 0.f, 0.f, 0.f);
        return;
    }

    // ---------------- strip + tail block: tile u = blockIdx.x --------------
    const int u = blockIdx.x;
    __shared__ float sm[2][16];
    __shared__ float Y[4];

    if (threadIdx.x >= 64) {
        // tail zeroing with the 192 spare threads
        const int idx = u * 192 + (threadIdx.x - 64);
        if (idx < NTAIL) {
            const int batch = idx / TAIL_F4;
            const int slot  = idx - batch * TAIL_F4;
            ((float4*)out)[(size_t)batch * BATCH_F4 + TAIL_BEG + slot] =
                make_float4(0.f, 0.f, 0.f, 0.f);
        }
    } else {
        const int c = threadIdx.x;  // channel 0..63

        // W = filters[0, c]
        float W[3][3];
#pragma unroll
        for (int j = 0; j < 3; ++j)
#pragma unroll
            for (int k = 0; k < 3; ++k)
                W[j][k] = filt[c * 9 + j * 3 + k];

        // U = G W G^T,  G = [[1,0,0],[.5,.5,1.2],[.5,-.5,.5],[0,0,1]]
        float s[4][3];
#pragma unroll
        for (int k = 0; k < 3; ++k) {
            s[0][k] = W[0][k];
            s[1][k] = 0.5f * W[0][k] + 0.5f * W[1][k] + 1.2f * W[2][k];
            s[2][k] = 0.5f * W[0][k] - 0.5f * W[1][k] + 0.5f * W[2][k];
            s[3][k] = W[2][k];
        }
        float U[4][4];
#pragma unroll
        for (int i = 0; i < 4; ++i) {
            U[i][0] = s[i][0];
            U[i][1] = 0.5f * s[i][0] + 0.5f * s[i][1] + 1.2f * s[i][2];
            U[i][2] = 0.5f * s[i][0] - 0.5f * s[i][1] + 0.5f * s[i][2];
            U[i][3] = s[i][2];
        }

        // X = x[0, c, 0:4, 2u:2u+4]
        float X[4][4];
        const float* xp = x + c * 4096 + 2 * u;
#pragma unroll
        for (int j = 0; j < 4; ++j)
#pragma unroll
            for (int k = 0; k < 4; ++k)
                X[j][k] = xp[j * 64 + k];

        // t = B^T X ; B^T rows: (1,0,0,0) (0,1,-1,1) (-1,1,1,0) (0,0,0,-1)
        float t[4][4];
#pragma unroll
        for (int k = 0; k < 4; ++k) {
            t[0][k] = X[0][k];
            t[1][k] = X[1][k] - X[2][k] + X[3][k];
            t[2][k] = -X[0][k] + X[1][k] + X[2][k];
            t[3][k] = -X[3][k];
        }
        // V = t B ; M_c = U .* V ; accumulate over channels
        float Macc[16];
#pragma unroll
        for (int i = 0; i < 4; ++i) {
            float v0 = t[i][0];
            float v1 = t[i][1] - t[i][2] + t[i][3];
            float v2 = -t[i][0] + t[i][1] + t[i][2];
            float v3 = -t[i][3];
            Macc[i * 4 + 0] = U[i][0] * v0;
            Macc[i * 4 + 1] = U[i][1] * v1;
            Macc[i * 4 + 2] = U[i][2] * v2;
            Macc[i * 4 + 3] = U[i][3] * v3;
        }

        // reduce 16 values over 64 channels (2 warps)
#pragma unroll
        for (int off = 16; off > 0; off >>= 1)
#pragma unroll
            for (int e = 0; e < 16; ++e)
                Macc[e] += __shfl_down_sync(0xffffffffu, Macc[e], off);

        const int warp = threadIdx.x >> 5;
        const int lane = threadIdx.x & 31;
        if (lane == 0) {
#pragma unroll
            for (int e = 0; e < 16; ++e) sm[warp][e] = Macc[e];
        }
    }
    __syncthreads();
    if (threadIdx.x == 0) {
        float M[4][4];
#pragma unroll
        for (int e = 0; e < 16; ++e) M[e >> 2][e & 3] = sm[0][e] + sm[1][e];
        // Y = AT M AT^T ; AT = [[1,1,1,0],[0,1,-1,-1]]
        float T0[4], T1[4];
#pragma unroll
        for (int k = 0; k < 4; ++k) {
            T0[k] = M[0][k] + M[1][k] + M[2][k];
            T1[k] = M[1][k] - M[2][k] - M[3][k];
        }
        Y[0] = T0[0] + T0[1] + T0[2];
        Y[1] = T0[1] - T0[2] - T0[3];
        Y[2] = T1[0] + T1[1] + T1[2];
        Y[3] = T1[1] - T1[2] - T1[3];
    }
    __syncthreads();

    // fan out: out[b, 0, {0,1}, 2u + {0,1}] for all 64 batches (float2 stores)
    if (threadIdx.x < 64) {
        const int b = threadIdx.x;
        float* op = out + (size_t)b * 246016 + 2 * u;
        *(float2*)(op)      = make_float2(Y[0], Y[1]);
        *(float2*)(op + 62) = make_float2(Y[2], Y[3]);
    }
}

extern "C" void kernel_launch(void* const* d_in, const int* in_sizes, int n_in,
                              void* d_out, int out_size) {
    const float* x    = (const float*)d_in[0];   // (64,64,64,64) f32
    const float* filt = (const float*)d_in[1];   // (64,64,3,3)   f32
    float* out = (float*)d_out;                  // (64,64,62,62) f32

    const int nblocks = NSTRIP + FPB * 64;       // 31 + 15360 = 15391
    wg_fused<<<nblocks, 256>>>(x, filt, out);
}